// round 12
// baseline (speedup 1.0000x reference)
#include <cuda_runtime.h>
#include <cuda_fp16.h>
#include <mma.h>
#include <cstdint>

using namespace nvcuda;

// DynamicConv: B=64, CIN=COUT=256, K=4 experts, 3x3 kernel on (L=1024 x 1).
// Width==1 + padding 1 => only kw=1 column contributes: per-batch GEMM
//   C[o,h] = sum_{ci,kh} Wagg[b][o,ci,kh] * x[b][ci,h-1+kh]   (M=256,N=1024,K=768)
// R11: fp16 single-pass wmma, 64x64 warp tiles (4 warps x 128 thr, 2 CTA/SM),
//      triple-buffered A cp.async, vectorized mix.

#define BATCH   64
#define CIN     256
#define COUT    256
#define CS      256
#define KEXP    4
#define HIDDEN  64
#define LEN     1024
#define TEMP    30.0f

#define TM      128            // o per CTA
#define TN      128            // h per CTA
#define CCH     64             // ci per K-chunk
#define NCB     (CIN / CCH)    // 4
#define NTILE   (3 * NCB)      // 12
#define NTHR    128

#define ASTR    72             // fp16 A row stride (144 B)
#define BSTR    72             // fp16 B row stride
#define BBSTR   24             // bias tile stride
#define XW      132            // x_s row width (floats): 0..127 body, 128 R-halo, 129 L-halo

// SMEM layout (bytes)
#define SM_ABUF(i) ((uint32_t)(18432u * (i)))   // 3 x 128x144
#define SM_B     55296          // B 136x144 = 19584
#define SM_X     74880          // x_s 64x132x4 = 33792
#define SM_TOTAL 108672
// bias tiles overlay B region (pre-mainloop only)
#define SM_ABH   SM_B
#define SM_BB    (SM_B + 6144)

__device__ float g_att[BATCH * KEXP];
__device__ float g_bmix[BATCH * COUT];
// Wagg fp16: [b][kh][cbi][o(256)][ci(64)]
#define WA_BSTRIDE (3 * NCB * COUT * CCH)   // 196608
__device__ __half g_wa[BATCH * WA_BSTRIDE];

__device__ __forceinline__ uint32_t smem_u32(const void* p) {
    uint32_t a;
    asm("{ .reg .u64 t; cvta.to.shared.u64 t, %1; cvt.u32.u64 %0, t; }" : "=r"(a) : "l"(p));
    return a;
}
__device__ __forceinline__ void cpa16(uint32_t d, const void* s) {
    asm volatile("cp.async.cg.shared.global [%0], [%1], 16;" :: "r"(d), "l"(s));
}
#define CP_COMMIT()  asm volatile("cp.async.commit_group;" ::: "memory")
#define CP_WAIT(n)   asm volatile("cp.async.wait_group %0;" :: "n"(n) : "memory")

// ---------------------------------------------------------------------------
// Kernel 1: routing MLP + softmax + mixed bias.
// ---------------------------------------------------------------------------
__global__ void routing_kernel(const float* __restrict__ cond,
                               const float* __restrict__ w1,
                               const float* __restrict__ w2,
                               const float* __restrict__ bias) {
    __shared__ float sh[HIDDEN];
    __shared__ float sl[KEXP];
    __shared__ float satt[KEXP];
    const int b = blockIdx.x;
    const int t = threadIdx.x;

    if (t < HIDDEN) {
        const float4* crow = (const float4*)(cond + b * CS);
        const float4* w1r  = (const float4*)(w1 + t * CS);
        float s0 = 0.0f, s1 = 0.0f;
#pragma unroll 8
        for (int i = 0; i < CS / 4; ++i) {
            float4 c4 = crow[i], w4 = w1r[i];
            s0 = fmaf(c4.x, w4.x, fmaf(c4.y, w4.y, s0));
            s1 = fmaf(c4.z, w4.z, fmaf(c4.w, w4.w, s1));
        }
        sh[t] = fmaxf(s0 + s1, 0.0f);
    }
    __syncthreads();
    if (t < KEXP) {
        const float* w2r = w2 + t * HIDDEN;
        float s = 0.0f;
#pragma unroll 8
        for (int i = 0; i < HIDDEN; ++i) s = fmaf(sh[i], w2r[i], s);
        sl[t] = s * (1.0f / TEMP);
    }
    __syncthreads();
    if (t == 0) {
        float m = sl[0];
#pragma unroll
        for (int k = 1; k < KEXP; ++k) m = fmaxf(m, sl[k]);
        float e[KEXP], sum = 0.0f;
#pragma unroll
        for (int k = 0; k < KEXP; ++k) { e[k] = expf(sl[k] - m); sum += e[k]; }
        float inv = 1.0f / sum;
#pragma unroll
        for (int k = 0; k < KEXP; ++k) {
            satt[k] = e[k] * inv;
            g_att[b * KEXP + k] = e[k] * inv;
        }
    }
    __syncthreads();
    {
        float v = 0.0f;
#pragma unroll
        for (int k = 0; k < KEXP; ++k) v = fmaf(satt[k], bias[k * COUT + t], v);
        g_bmix[b * COUT + t] = v;
    }
}

// ---------------------------------------------------------------------------
// Kernel 2: mix experts -> g_wa fp16. Thread = (kh,cbi,o,8-ci group).
// 16B coalesced stores, 64-batch register loop.
// ---------------------------------------------------------------------------
__global__ void mix_kernel(const float* __restrict__ weight) {
    const int idx = blockIdx.x * 256 + threadIdx.x;   // 0 .. 3*4*256*8-1
    const int c8  = idx & 7;                          // 8-ci group
    const int o   = (idx >> 3) & 255;
    const int cbi = (idx >> 11) & 3;
    const int kh  = idx >> 13;                        // 0..2
    const int ci0 = cbi * CCH + 8 * c8;

    float w[KEXP][8];
#pragma unroll
    for (int k = 0; k < KEXP; ++k) {
        const float* wp = weight + (((size_t)(k * COUT + o) * CIN + ci0) * 3 + kh) * 3 + 1;
#pragma unroll
        for (int c = 0; c < 8; ++c) w[k][c] = wp[c * 9];
    }

    const size_t obase = (((size_t)kh * NCB + cbi) * COUT + o) * CCH + 8 * c8;
    for (int b = 0; b < BATCH; ++b) {
        const float* a = g_att + b * KEXP;
        float a0 = a[0], a1 = a[1], a2 = a[2], a3 = a[3];
        __half2 h[4];
#pragma unroll
        for (int p = 0; p < 4; ++p) {
            float v0 = a0 * w[0][2*p]   + a1 * w[1][2*p]   + a2 * w[2][2*p]   + a3 * w[3][2*p];
            float v1 = a0 * w[0][2*p+1] + a1 * w[1][2*p+1] + a2 * w[2][2*p+1] + a3 * w[3][2*p+1];
            h[p] = __floats2half2_rn(v0, v1);
        }
        *(uint4*)(g_wa + (size_t)b * WA_BSTRIDE + obase) = *(uint4*)h;
    }
}

// ---------------------------------------------------------------------------
// Kernel 3: wmma fp16 conv. grid (8 h-tiles, 2 o-tiles, 64 b), 128 threads.
// 4 warps, 64x64 warp tile, triple-buffered A.
// ---------------------------------------------------------------------------
__global__ void __launch_bounds__(NTHR, 2)
conv_kernel(const float* __restrict__ x, float* __restrict__ out) {
    extern __shared__ char smem[];
    const uint32_t sb = smem_u32(smem);
    const int tid = threadIdx.x;
    const int wid = tid >> 5;
    const int lid = tid & 31;
    const int hb  = blockIdx.x * TN;
    const int ob  = blockIdx.y * TM;
    const int b   = blockIdx.z;
    const int wm  = wid >> 1;     // 0..1 -> 64 o-rows
    const int wn  = wid & 1;      // 0..1 -> 64 h-cols

    const float* xb = x + (size_t)b * CIN * LEN;
    float* x_s = (float*)(smem + SM_X);

    auto issue_A = [&](int j) {
        const uint32_t bufoff = SM_ABUF(j % 3);
        const int cbi = j / 3;
        const int kh  = j - 3 * cbi;
        const uint4* gs = (const uint4*)(g_wa +
            ((((size_t)b * 3 + kh) * NCB + cbi) * COUT + ob) * CCH);
#pragma unroll
        for (int t = 0; t < 8; ++t) {
            int idx = tid + t * NTHR;         // 1024 chunks = 128 rows x 8
            int r = idx >> 3, c = idx & 7;
            cpa16(sb + bufoff + r * 144 + c * 16, gs + idx);
        }
    };
    auto issue_X = [&](int cbi) {
#pragma unroll
        for (int t = 0; t < 16; ++t) {
            int idx = tid + t * NTHR;         // 2048 chunks = 64 rows x 32
            int r = idx >> 5, c = idx & 31;
            cpa16(sb + SM_X + r * (XW * 4) + c * 16,
                  xb + (cbi * CCH + r) * LEN + hb + c * 4);
        }
        {                                     // 128 halo slots (plain STS)
            int r = tid & 63, side = tid >> 6;
            int h = side ? (hb + 128) : (hb - 1);
            float v = ((unsigned)h < (unsigned)LEN) ? xb[(cbi * CCH + r) * LEN + h] : 0.0f;
            x_s[r * XW + (side ? 128 : 129)] = v;
        }
    };

    // prologue groups: g0={A0,X0}, g1={A1}
    issue_A(0);
    issue_X(0);
    CP_COMMIT();
    issue_A(1);
    CP_COMMIT();

    // ---- accumulators + exact-bias K=16 GEMM term (tiles overlay B region) ----
    wmma::fragment<wmma::accumulator, 16, 16, 16, float> acc[4][4];
#pragma unroll
    for (int mt = 0; mt < 4; ++mt)
#pragma unroll
        for (int nt = 0; nt < 4; ++nt) wmma::fill_fragment(acc[mt][nt], 0.0f);

    for (int i = tid; i < 12288 / 4; i += NTHR)
        ((uint32_t*)(smem + SM_ABH))[i] = 0;
    __syncthreads();
    {
        float bm = g_bmix[b * COUT + ob + tid];
        __half h = __float2half_rn(bm);
        __half* hA = (__half*)(smem + SM_ABH);
        __half* hB = (__half*)(smem + SM_BB);
        hA[tid * BBSTR + 0] = h;
        hA[tid * BBSTR + 1] = __float2half_rn(bm - __half2float(h));
        hB[tid * BBSTR + 0] = __float2half_rn(1.0f);
        hB[tid * BBSTR + 1] = __float2half_rn(1.0f);
    }
    __syncthreads();
    {
        wmma::fragment<wmma::matrix_a, 16, 16, 16, __half, wmma::row_major> fa;
        wmma::fragment<wmma::matrix_b, 16, 16, 16, __half, wmma::col_major> fb;
#pragma unroll
        for (int nt = 0; nt < 4; ++nt) {
            wmma::load_matrix_sync(fb,
                (const __half*)(smem + SM_BB) + (wn * 64 + nt * 16) * BBSTR, BBSTR);
#pragma unroll
            for (int mt = 0; mt < 4; ++mt) {
                wmma::load_matrix_sync(fa,
                    (const __half*)(smem + SM_ABH) + (wm * 64 + mt * 16) * BBSTR, BBSTR);
                wmma::mma_sync(acc[mt][nt], fa, fb, acc[mt][nt]);
            }
        }
    }
    __syncthreads();           // bias tiles dead -> B region reusable

    CP_WAIT(1);                // g0 done: A0 + X0 resident (g1 may pend)
    __syncthreads();

    // ---- mainloop ----
    for (int cbi = 0; cbi < NCB; ++cbi) {
        // build B tile [n][ci] fp16 from x_s (conflict-free both sides)
        {
            const int nl = lid >> 2, cl = lid & 3;
            for (int job = wid; job < 8 * 17; job += 4) {
                const int cpb  = job / 17;
                const int nblk = job - 17 * cpb;
                const int n  = nblk * 8 + nl;
                const int cp = cpb * 4 + cl;          // ci pair 0..31
                if (n < 130) {
                    const int jj = (n == 0) ? 129 : (n - 1);
                    float v0 = x_s[(2 * cp    ) * XW + jj];
                    float v1 = x_s[(2 * cp + 1) * XW + jj];
                    *(__half2*)(smem + SM_B + n * 144 + cp * 4) =
                        __floats2half2_rn(v0, v1);
                }
            }
        }
        __syncthreads();

        for (int kh = 0; kh < 3; ++kh) {
            const int j = cbi * 3 + kh;
            if (j + 2 < NTILE) issue_A(j + 2);
            if (kh == 0 && cbi + 1 < NCB) issue_X(cbi + 1);
            CP_COMMIT();                 // group g_{j+2}
            CP_WAIT(2);                  // groups <= g_j done: A(j) resident
            __syncthreads();

            const __half* A  = (const __half*)(smem + SM_ABUF(j % 3));
            const __half* Bp = (const __half*)(smem + SM_B);

#pragma unroll
            for (int ks = 0; ks < 4; ++ks) {
                wmma::fragment<wmma::matrix_a, 16, 16, 16, __half, wmma::row_major> fa[4];
                wmma::fragment<wmma::matrix_b, 16, 16, 16, __half, wmma::col_major> fb;
#pragma unroll
                for (int mt = 0; mt < 4; ++mt)
                    wmma::load_matrix_sync(fa[mt],
                        A + (wm * 64 + mt * 16) * ASTR + ks * 16, ASTR);
#pragma unroll
                for (int nt = 0; nt < 4; ++nt) {
                    wmma::load_matrix_sync(fb,
                        Bp + (wn * 64 + nt * 16 + kh) * BSTR + ks * 16, BSTR);
#pragma unroll
                    for (int mt = 0; mt < 4; ++mt)
                        wmma::mma_sync(acc[mt][nt], fa[mt], fb, acc[mt][nt]);
                }
            }
            __syncthreads();   // frag reads done: buf (j)%3 free for reuse
        }
    }

    // ---- epilogue: bias already in acc; direct global store ----
    float* op = out + ((size_t)(b * COUT + ob + wm * 64)) * LEN + hb + wn * 64;
#pragma unroll
    for (int mt = 0; mt < 4; ++mt)
#pragma unroll
        for (int nt = 0; nt < 4; ++nt)
            wmma::store_matrix_sync(op + (size_t)mt * 16 * LEN + nt * 16,
                                    acc[mt][nt], LEN, wmma::mem_row_major);
}

// ---------------------------------------------------------------------------
extern "C" void kernel_launch(void* const* d_in, const int* in_sizes, int n_in,
                              void* d_out, int out_size) {
    const float* x      = (const float*)d_in[0];   // (64,256,1024,1)
    const float* cond   = (const float*)d_in[1];   // (64,256)
    const float* w1     = (const float*)d_in[2];   // (64,256)
    const float* w2     = (const float*)d_in[3];   // (4,64)
    const float* weight = (const float*)d_in[4];   // (4,256,256,3,3)
    const float* bias   = (const float*)d_in[5];   // (4,256)
    float* out = (float*)d_out;                    // (64,256,1024,1)

    static int attr_set = 0;
    if (!attr_set) {
        cudaFuncSetAttribute(conv_kernel,
                             cudaFuncAttributeMaxDynamicSharedMemorySize, SM_TOTAL);
        attr_set = 1;
    }

    routing_kernel<<<BATCH, 256>>>(cond, w1, w2, bias);
    mix_kernel<<<(3 * NCB * COUT * 8) / 256, 256>>>(weight);
    conv_kernel<<<dim3(LEN / TN, COUT / TM, BATCH), NTHR, SM_TOTAL>>>(x, out);
}